// round 12
// baseline (speedup 1.0000x reference)
#include <cuda_runtime.h>
#include <math.h>

#define NQ       10
#define DIM      1024
#define NL       3
#define NG       (NL * NQ)
#define WPB      4
#define PI_F     3.14159265358979f

// ---------------- packed f32x2 helpers (sm_103a) ----------------
union F2U { float2 f; unsigned long long u; };

__device__ __forceinline__ float2 f2mul(float2 a, float2 b) {
    F2U A, B, D; A.f = a; B.f = b;
    asm("mul.rn.f32x2 %0, %1, %2;" : "=l"(D.u) : "l"(A.u), "l"(B.u));
    return D.f;
}
__device__ __forceinline__ float2 f2fma(float2 a, float2 b, float2 c) {
    F2U A, B, C, D; A.f = a; B.f = b; C.f = c;
    asm("fma.rn.f32x2 %0, %1, %2, %3;" : "=l"(D.u) : "l"(A.u), "l"(B.u), "l"(C.u));
    return D.f;
}
__device__ __forceinline__ float2 cmul(float2 a, float2 b) {
    return make_float2(a.x * b.x - a.y * b.y, a.x * b.y + a.y * b.x);
}

// XOR bank swizzle (conflict-free for all patterns below; verified).
__device__ __forceinline__ int physk(int k) { return k ^ ((k >> 5) & 15); }

// Gate coefficients packed per u-element as (x, x, -y, y); order u00,u01,u10,u11.
__device__ float4 g_gco[NG][4];

// ---------------- prep: fuse RZ*RY*RX per (layer,qubit) ----------------
__global__ void vq_prep(const float* __restrict__ w) {
    const int t = threadIdx.x;
    if (t >= NG) return;
    const float ax = w[t * 3 + 0], ay = w[t * 3 + 1], az = w[t * 3 + 2];
    float ca, sa, cb, sb, cg, sg;
    sincosf(0.5f * ax, &sa, &ca);
    sincosf(0.5f * ay, &sb, &cb);
    sincosf(0.5f * az, &sg, &cg);
    const float2 M00 = make_float2( cb * ca,  sb * sa);
    const float2 M01 = make_float2(-sb * ca, -cb * sa);
    const float2 M10 = make_float2( sb * ca, -cb * sa);
    const float2 M11 = make_float2( cb * ca, -sb * sa);
    const float2 e0 = make_float2(cg, -sg);
    const float2 e1 = make_float2(cg,  sg);
    const float2 u00 = cmul(e0, M00), u01 = cmul(e0, M01);
    const float2 u10 = cmul(e1, M10), u11 = cmul(e1, M11);
    g_gco[t][0] = make_float4(u00.x, u00.x, -u00.y, u00.y);
    g_gco[t][1] = make_float4(u01.x, u01.x, -u01.y, u01.y);
    g_gco[t][2] = make_float4(u10.x, u10.x, -u10.y, u10.y);
    g_gco[t][3] = make_float4(u11.x, u11.x, -u11.y, u11.y);
}

// Apply fused gate with register-bit mask RM to 32 register-resident amps.
template<int RM>
__device__ __forceinline__ void apply_gate32(float2 a[32], int g) {
    const float4 q0 = __ldg(&g_gco[g][0]);
    const float4 q1 = __ldg(&g_gco[g][1]);
    const float4 q2 = __ldg(&g_gco[g][2]);
    const float4 q3 = __ldg(&g_gco[g][3]);
    const float2 u00x = make_float2(q0.x, q0.y), u00m = make_float2(q0.z, q0.w);
    const float2 u01x = make_float2(q1.x, q1.y), u01m = make_float2(q1.z, q1.w);
    const float2 u10x = make_float2(q2.x, q2.y), u10m = make_float2(q2.z, q2.w);
    const float2 u11x = make_float2(q3.x, q3.y), u11m = make_float2(q3.z, q3.w);
#pragma unroll
    for (int r = 0; r < 32; ++r) {
        if (r & RM) continue;
        const float2 a0 = a[r];
        const float2 a1 = a[r | RM];
        const float2 s0 = make_float2(a0.y, a0.x);
        const float2 s1 = make_float2(a1.y, a1.x);
        float2 r0 = f2mul(u00x, a0);
        r0 = f2fma(u00m, s0, r0);
        r0 = f2fma(u01x, a1, r0);
        r0 = f2fma(u01m, s1, r0);
        float2 r1 = f2mul(u10x, a0);
        r1 = f2fma(u10m, s0, r1);
        r1 = f2fma(u11x, a1, r1);
        r1 = f2fma(u11m, s1, r1);
        a[r]      = r0;
        a[r | RM] = r1;
    }
}

// ---------------- main: 1 warp = 1 batch element, 32 amps/thread ----------------
// Layout A: k = [L4..L0 | r4..r0]  (reg bits = qubits 5..9)
// Layout B: k = [r4..r0 | L4..L0]  (reg bits = qubits 0..4)
// minocc 5 -> 102-reg cap: live set ~95, should be spill-free.
__global__ __launch_bounds__(128, 5)
void vq_main(const float* __restrict__ x, float* __restrict__ out) {
    __shared__ float2 sh[WPB][DIM];        // 8 KB per warp

    const int t  = threadIdx.x;
    const int wi = t >> 5;
    const int L  = t & 31;
    const int b  = blockIdx.x * WPB + wi;
    float2* const S = sh[wi];

    // ---- encoding angles (lanes 0..9 compute, shfl broadcast) ----
    float c = 1.0f, s = 0.0f;
    if (L < NQ) {
        const float a = tanhf(x[b * NQ + L]) * PI_F;
        sincosf(0.5f * a, &s, &c);
    }
    float cq[NQ], sq[NQ];
#pragma unroll
    for (int q = 0; q < NQ; ++q) {
        cq[q] = __shfl_sync(0xffffffffu, c, q);
        sq[q] = __shfl_sync(0xffffffffu, s, q);
    }

    // ---- initial state = enc evaluated at P(k), k in layout A ----
    // P(k) closed form: hi5 = L^(L>>1) ^ (r0 ? 0x18 : 0),  bit i <-> qubit 4-i
    //                   lo5 = (r^(r>>1)) ^ (L0<<4),         bit i <-> qubit 9-i
    const int hb = (L ^ (L >> 1)) & 31;
    float hE = 1.0f, hO = 1.0f;
#pragma unroll
    for (int i = 0; i < 5; ++i) {
        hE *= ((hb >> i) & 1)          ? sq[4 - i] : cq[4 - i];
        hO *= (((hb ^ 0x18) >> i) & 1) ? sq[4 - i] : cq[4 - i];
    }
    float2 a[32];
#pragma unroll
    for (int r = 0; r < 32; ++r) {
        const int lo = (r ^ (r >> 1)) ^ ((L & 1) << 4);
        float f = (r & 1) ? hO : hE;
#pragma unroll
        for (int i = 0; i < 5; ++i)
            f *= ((lo >> i) & 1) ? sq[9 - i] : cq[9 - i];
        a[r] = make_float2(f, 0.0f);
    }

    // ---- layers ----
#pragma unroll
    for (int l = 0; l < NL; ++l) {
        if (l > 0) {
            // store layout B, gather through CNOT-ring perm into layout A
            __syncwarp();
#pragma unroll
            for (int r = 0; r < 32; ++r) S[physk((r << 5) | L)] = a[r];
            __syncwarp();
#pragma unroll
            for (int r = 0; r < 32; ++r) {
                const int k = (L << 5) | r;
                a[r] = S[physk(k ^ (k >> 1) ^ ((-(k & 1)) & 0x300))];
            }
        }

        // layout A gates, small-mask first (early start after gather):
        // q9..q5 <-> masks 1,2,4,8,16
        apply_gate32<1 >(a, l * NQ + 9);
        apply_gate32<2 >(a, l * NQ + 8);
        apply_gate32<4 >(a, l * NQ + 7);
        apply_gate32<8 >(a, l * NQ + 6);
        apply_gate32<16>(a, l * NQ + 5);

        // transpose A -> B
        __syncwarp();
#pragma unroll
        for (int r = 0; r < 32; ++r) S[physk((L << 5) | r)] = a[r];
        __syncwarp();
#pragma unroll
        for (int r = 0; r < 32; ++r) a[r] = S[physk((r << 5) | L)];

        // layout B gates, small-mask first: q4..q0 <-> masks 1,2,4,8,16
        apply_gate32<1 >(a, l * NQ + 4);
        apply_gate32<2 >(a, l * NQ + 3);
        apply_gate32<4 >(a, l * NQ + 2);
        apply_gate32<8 >(a, l * NQ + 1);
        apply_gate32<16>(a, l * NQ + 0);
    }

    // ---- Z expectations (layout B):
    // q0..q4 <-> r bits 4..0 ; q5..q9 <-> L bits 4..0
    float T = 0.0f, A0 = 0.0f, A1 = 0.0f, A2 = 0.0f, A3 = 0.0f, A4 = 0.0f;
#pragma unroll
    for (int r = 0; r < 32; ++r) {
        const float p = a[r].x * a[r].x + a[r].y * a[r].y;
        T  += p;
        A0 += (r & 16) ? -p : p;
        A1 += (r & 8)  ? -p : p;
        A2 += (r & 4)  ? -p : p;
        A3 += (r & 2)  ? -p : p;
        A4 += (r & 1)  ? -p : p;
    }
    float red[NQ];
    red[0] = A0;  red[1] = A1;  red[2] = A2;  red[3] = A3;  red[4] = A4;
    red[5] = (L & 16) ? -T : T;
    red[6] = (L & 8)  ? -T : T;
    red[7] = (L & 4)  ? -T : T;
    red[8] = (L & 2)  ? -T : T;
    red[9] = (L & 1)  ? -T : T;

#pragma unroll
    for (int q = 0; q < NQ; ++q) {
#pragma unroll
        for (int off = 16; off > 0; off >>= 1)
            red[q] += __shfl_xor_sync(0xffffffffu, red[q], off);
    }
    if (L == 0) {
#pragma unroll
        for (int q = 0; q < NQ; ++q)
            out[b * NQ + q] = red[q];
    }
}

extern "C" void kernel_launch(void* const* d_in, const int* in_sizes, int n_in,
                              void* d_out, int out_size) {
    const float* x = (const float*)d_in[0];
    const float* w = (const float*)d_in[1];
    if (n_in >= 2 && in_sizes[0] == NG * 3 && in_sizes[1] != NG * 3) {
        x = (const float*)d_in[1];
        w = (const float*)d_in[0];
    }
    // 5 blocks/SM need 165 KB smem: bias the carveout high.
    static bool attr_set = false;
    if (!attr_set) {
        cudaFuncSetAttribute(vq_main,
                             cudaFuncAttributePreferredSharedMemoryCarveout, 100);
        attr_set = true;
    }
    const int batch = out_size / NQ;            // 16384
    vq_prep<<<1, 32>>>(w);
    vq_main<<<batch / WPB, 128>>>(x, (float*)d_out);
}

// round 14
// speedup vs baseline: 2.3483x; 2.3483x over previous
#include <cuda_runtime.h>
#include <math.h>

#define NQ       10
#define DIM      1024
#define NL       3
#define NG       (NL * NQ)
#define WPB      4
#define PI_F     3.14159265358979f

// ---------------- packed f32x2 helpers (sm_103a) ----------------
union F2U { float2 f; unsigned long long u; };

__device__ __forceinline__ float2 f2mul(float2 a, float2 b) {
    F2U A, B, D; A.f = a; B.f = b;
    asm("mul.rn.f32x2 %0, %1, %2;" : "=l"(D.u) : "l"(A.u), "l"(B.u));
    return D.f;
}
__device__ __forceinline__ float2 f2fma(float2 a, float2 b, float2 c) {
    F2U A, B, C, D; A.f = a; B.f = b; C.f = c;
    asm("fma.rn.f32x2 %0, %1, %2, %3;" : "=l"(D.u) : "l"(A.u), "l"(B.u), "l"(C.u));
    return D.f;
}
__device__ __forceinline__ float2 cmul(float2 a, float2 b) {
    return make_float2(a.x * b.x - a.y * b.y, a.x * b.y + a.y * b.x);
}

// XOR bank swizzle (conflict-free for all patterns below; verified).
__device__ __forceinline__ int physk(int k) { return k ^ ((k >> 5) & 15); }

// Gate coefficients packed per u-element as (x, x, -y, y); order u00,u01,u10,u11.
__device__ float4 g_gco[NG][4];

// ---------------- prep: fuse RZ*RY*RX per (layer,qubit) ----------------
__global__ void vq_prep(const float* __restrict__ w) {
    const int t = threadIdx.x;
    if (t >= NG) return;
    const float ax = w[t * 3 + 0], ay = w[t * 3 + 1], az = w[t * 3 + 2];
    float ca, sa, cb, sb, cg, sg;
    sincosf(0.5f * ax, &sa, &ca);
    sincosf(0.5f * ay, &sb, &cb);
    sincosf(0.5f * az, &sg, &cg);
    const float2 M00 = make_float2( cb * ca,  sb * sa);
    const float2 M01 = make_float2(-sb * ca, -cb * sa);
    const float2 M10 = make_float2( sb * ca, -cb * sa);
    const float2 M11 = make_float2( cb * ca, -sb * sa);
    const float2 e0 = make_float2(cg, -sg);
    const float2 e1 = make_float2(cg,  sg);
    const float2 u00 = cmul(e0, M00), u01 = cmul(e0, M01);
    const float2 u10 = cmul(e1, M10), u11 = cmul(e1, M11);
    g_gco[t][0] = make_float4(u00.x, u00.x, -u00.y, u00.y);
    g_gco[t][1] = make_float4(u01.x, u01.x, -u01.y, u01.y);
    g_gco[t][2] = make_float4(u10.x, u10.x, -u10.y, u10.y);
    g_gco[t][3] = make_float4(u11.x, u11.x, -u11.y, u11.y);
}

// Apply fused gate with register-bit mask RM to 32 register-resident amps.
template<int RM>
__device__ __forceinline__ void apply_gate32(float2 a[32], int g) {
    const float4 q0 = __ldg(&g_gco[g][0]);
    const float4 q1 = __ldg(&g_gco[g][1]);
    const float4 q2 = __ldg(&g_gco[g][2]);
    const float4 q3 = __ldg(&g_gco[g][3]);
    const float2 u00x = make_float2(q0.x, q0.y), u00m = make_float2(q0.z, q0.w);
    const float2 u01x = make_float2(q1.x, q1.y), u01m = make_float2(q1.z, q1.w);
    const float2 u10x = make_float2(q2.x, q2.y), u10m = make_float2(q2.z, q2.w);
    const float2 u11x = make_float2(q3.x, q3.y), u11m = make_float2(q3.z, q3.w);
#pragma unroll
    for (int r = 0; r < 32; ++r) {
        if (r & RM) continue;
        const float2 a0 = a[r];
        const float2 a1 = a[r | RM];
        const float2 s0 = make_float2(a0.y, a0.x);
        const float2 s1 = make_float2(a1.y, a1.x);
        float2 r0 = f2mul(u00x, a0);
        r0 = f2fma(u00m, s0, r0);
        r0 = f2fma(u01x, a1, r0);
        r0 = f2fma(u01m, s1, r0);
        float2 r1 = f2mul(u10x, a0);
        r1 = f2fma(u10m, s0, r1);
        r1 = f2fma(u11x, a1, r1);
        r1 = f2fma(u11m, s1, r1);
        a[r]      = r0;
        a[r | RM] = r1;
    }
}

// ---------------- main: 1 warp = 1 batch element, 32 amps/thread ----------------
// Layout A: k = [L4..L0 | r4..r0]  (reg bits = qubits 5..9)
// Layout B: k = [r4..r0 | L4..L0]  (reg bits = qubits 0..4)
// minocc 4 -> 128-reg budget (R6's proven spill-free allocation).
__global__ __launch_bounds__(128, 4)
void vq_main(const float* __restrict__ x, float* __restrict__ out) {
    __shared__ float2 sh[WPB][DIM];        // 8 KB per warp

    const int t  = threadIdx.x;
    const int wi = t >> 5;
    const int L  = t & 31;
    const int b  = blockIdx.x * WPB + wi;
    float2* const S = sh[wi];

    // ---- encoding angles (lanes 0..9 compute, shfl broadcast) ----
    float c = 1.0f, s = 0.0f;
    if (L < NQ) {
        const float a = tanhf(x[b * NQ + L]) * PI_F;
        sincosf(0.5f * a, &s, &c);
    }
    float cq[NQ], sq[NQ];
#pragma unroll
    for (int q = 0; q < NQ; ++q) {
        cq[q] = __shfl_sync(0xffffffffu, c, q);
        sq[q] = __shfl_sync(0xffffffffu, s, q);
    }

    // ---- initial state = enc evaluated at P(k), k in layout A ----
    // P(k) closed form: hi5 = L^(L>>1) ^ (r0 ? 0x18 : 0),  bit i <-> qubit 4-i
    //                   lo5 = (r^(r>>1)) ^ (L0<<4),         bit i <-> qubit 9-i
    const int hb = (L ^ (L >> 1)) & 31;
    float hE = 1.0f, hO = 1.0f;
#pragma unroll
    for (int i = 0; i < 5; ++i) {
        hE *= ((hb >> i) & 1)          ? sq[4 - i] : cq[4 - i];
        hO *= (((hb ^ 0x18) >> i) & 1) ? sq[4 - i] : cq[4 - i];
    }
    float2 a[32];
#pragma unroll
    for (int r = 0; r < 32; ++r) {
        const int lo = (r ^ (r >> 1)) ^ ((L & 1) << 4);
        float f = (r & 1) ? hO : hE;
#pragma unroll
        for (int i = 0; i < 5; ++i)
            f *= ((lo >> i) & 1) ? sq[9 - i] : cq[9 - i];
        a[r] = make_float2(f, 0.0f);
    }

    // ---- layers ----
#pragma unroll
    for (int l = 0; l < NL; ++l) {
        if (l > 0) {
            // store layout B, gather through CNOT-ring perm into layout A
            __syncwarp();
#pragma unroll
            for (int r = 0; r < 32; ++r) S[physk((r << 5) | L)] = a[r];
            __syncwarp();
#pragma unroll
            for (int r = 0; r < 32; ++r) {
                const int k = (L << 5) | r;
                a[r] = S[physk(k ^ (k >> 1) ^ ((-(k & 1)) & 0x300))];
            }
        }

        // layout A gates, small-mask first (early start after gather):
        // q9..q5 <-> masks 1,2,4,8,16
        apply_gate32<1 >(a, l * NQ + 9);
        apply_gate32<2 >(a, l * NQ + 8);
        apply_gate32<4 >(a, l * NQ + 7);
        apply_gate32<8 >(a, l * NQ + 6);
        apply_gate32<16>(a, l * NQ + 5);

        // transpose A -> B
        __syncwarp();
#pragma unroll
        for (int r = 0; r < 32; ++r) S[physk((L << 5) | r)] = a[r];
        __syncwarp();
#pragma unroll
        for (int r = 0; r < 32; ++r) a[r] = S[physk((r << 5) | L)];

        // layout B gates, small-mask first: q4..q0 <-> masks 1,2,4,8,16
        apply_gate32<1 >(a, l * NQ + 4);
        apply_gate32<2 >(a, l * NQ + 3);
        apply_gate32<4 >(a, l * NQ + 2);
        apply_gate32<8 >(a, l * NQ + 1);
        apply_gate32<16>(a, l * NQ + 0);
    }

    // ---- Z expectations (layout B):
    // q0..q4 <-> r bits 4..0 ; q5..q9 <-> L bits 4..0
    float T = 0.0f, A0 = 0.0f, A1 = 0.0f, A2 = 0.0f, A3 = 0.0f, A4 = 0.0f;
#pragma unroll
    for (int r = 0; r < 32; ++r) {
        const float p = a[r].x * a[r].x + a[r].y * a[r].y;
        T  += p;
        A0 += (r & 16) ? -p : p;
        A1 += (r & 8)  ? -p : p;
        A2 += (r & 4)  ? -p : p;
        A3 += (r & 2)  ? -p : p;
        A4 += (r & 1)  ? -p : p;
    }
    float red[NQ];
    red[0] = A0;  red[1] = A1;  red[2] = A2;  red[3] = A3;  red[4] = A4;
    red[5] = (L & 16) ? -T : T;
    red[6] = (L & 8)  ? -T : T;
    red[7] = (L & 4)  ? -T : T;
    red[8] = (L & 2)  ? -T : T;
    red[9] = (L & 1)  ? -T : T;

#pragma unroll
    for (int q = 0; q < NQ; ++q) {
#pragma unroll
        for (int off = 16; off > 0; off >>= 1)
            red[q] += __shfl_xor_sync(0xffffffffu, red[q], off);
    }
    if (L == 0) {
#pragma unroll
        for (int q = 0; q < NQ; ++q)
            out[b * NQ + q] = red[q];
    }
}

extern "C" void kernel_launch(void* const* d_in, const int* in_sizes, int n_in,
                              void* d_out, int out_size) {
    const float* x = (const float*)d_in[0];
    const float* w = (const float*)d_in[1];
    if (n_in >= 2 && in_sizes[0] == NG * 3 && in_sizes[1] != NG * 3) {
        x = (const float*)d_in[1];
        w = (const float*)d_in[0];
    }
    const int batch = out_size / NQ;            // 16384
    vq_prep<<<1, 32>>>(w);
    vq_main<<<batch / WPB, 128>>>(x, (float*)d_out);
}